// round 10
// baseline (speedup 1.0000x reference)
#include <cuda_runtime.h>
#include <cuda_bf16.h>
#include <math.h>
#include <stdint.h>

#define B_  64
#define E_  512
#define H_  512
#define V_  32000
#define T_  32
#define G4  2048   // 4*H

typedef unsigned long long ull;

// ---------------- persistent device state ----------------
__device__ __align__(16) float g_h[2][B_ * H_];     // double-buffered hidden state
__device__ __align__(16) float g_c[B_ * H_];        // cell state
__device__ __align__(16) float g_gates[4][B_ * G4]; // planes: ih-k0, ih-k1, hh-k0, hh-k1
__device__ ull g_amax[2][B_];                       // packed argmax accumulators
// bf16 2-term splits
__device__ __align__(16) __nv_bfloat16 g_Wb1[(size_t)V_ * 512];   // lin_W hi
__device__ __align__(16) __nv_bfloat16 g_Wb2[(size_t)V_ * 512];   // lin_W lo
__device__ __align__(16) __nv_bfloat16 g_Ib1[2048 * 512];         // W_ih hi
__device__ __align__(16) __nv_bfloat16 g_Ib2[2048 * 512];         // W_ih lo
__device__ __align__(16) __nv_bfloat16 g_Hb1[2048 * 512];         // W_hh hi
__device__ __align__(16) __nv_bfloat16 g_Hb2[2048 * 512];         // W_hh lo
__device__ __align__(16) __nv_bfloat16 g_hb[2][B_ * 512];         // h(t) splits [term][b*512+k]

__device__ __forceinline__ unsigned fkey(float f) {
    unsigned u = __float_as_uint(f);
    return (u & 0x80000000u) ? ~u : (u | 0x80000000u);
}
__device__ __forceinline__ uint32_t smem_u32(const void* p) {
    uint32_t a;
    asm("{ .reg .u64 t; cvta.to.shared.u64 t, %1; cvt.u32.u64 %0, t; }" : "=r"(a) : "l"(p));
    return a;
}
__device__ __forceinline__ void ldsm4(uint32_t* r, uint32_t addr) {
    asm volatile("ldmatrix.sync.aligned.m8n8.x4.shared.b16 {%0,%1,%2,%3}, [%4];"
        : "=r"(r[0]), "=r"(r[1]), "=r"(r[2]), "=r"(r[3]) : "r"(addr));
}
__device__ __forceinline__ void mma16816(float* d, const uint32_t* a, uint32_t b0, uint32_t b1) {
    asm volatile("mma.sync.aligned.m16n8k16.row.col.f32.bf16.bf16.f32 "
        "{%0,%1,%2,%3}, {%4,%5,%6,%7}, {%8,%9}, {%0,%1,%2,%3};"
        : "+f"(d[0]), "+f"(d[1]), "+f"(d[2]), "+f"(d[3])
        : "r"(a[0]), "r"(a[1]), "r"(a[2]), "r"(a[3]), "r"(b0), "r"(b1));
}
__device__ __forceinline__ void cpasync16(uint32_t dst, const void* src) {
    asm volatile("cp.async.cg.shared.global [%0], [%1], 16;" :: "r"(dst), "l"(src));
}
#define SW128(o) ((o) ^ (((o) >> 3) & 0x70))

// Dynamic smem layout (per buffer): W1 16K | W2 16K | H1 8K | H2 8K
#define DSM_STRIDE 49152
#define DSM_W1 0
#define DSM_W2 16384
#define DSM_H1 32768
#define DSM_H2 40960
#define DSM_TOT (2 * DSM_STRIDE)

// =========================================================
// k_splitall: one prologue kernel producing every bf16 split.
// =========================================================
__global__ __launch_bounds__(256) void k_splitall(
    const float* __restrict__ lin_W, const float* __restrict__ W_ih,
    const float* __restrict__ W_hh,  const float* __restrict__ features)
{
    const int bid = blockIdx.x;
    const int tid = threadIdx.x;
    if (bid < 64000) {
        size_t i = (size_t)bid * 256 + tid;
        float w = lin_W[i];
        __nv_bfloat16 h1 = __float2bfloat16(w);
        g_Wb1[i] = h1;
        g_Wb2[i] = __float2bfloat16(w - __bfloat162float(h1));
    } else if (bid < 68096) {
        int i = (bid - 64000) * 256 + tid;
        float w = W_ih[i];
        __nv_bfloat16 h1 = __float2bfloat16(w);
        g_Ib1[i] = h1;
        g_Ib2[i] = __float2bfloat16(w - __bfloat162float(h1));
    } else if (bid < 72192) {
        int i = (bid - 68096) * 256 + tid;
        float w = W_hh[i];
        __nv_bfloat16 h1 = __float2bfloat16(w);
        g_Hb1[i] = h1;
        g_Hb2[i] = __float2bfloat16(w - __bfloat162float(h1));
    } else {
        int i = (bid - 72192) * 256 + tid;
        float f = features[i];
        __nv_bfloat16 h1 = __float2bfloat16(f);
        g_hb[0][i] = h1;
        g_hb[1][i] = __float2bfloat16(f - __bfloat162float(h1));
    }
}

// ---- shared staging: 128 w-rows x 64k + 64 h-rows x 64k (from g_hb) ----
__device__ __forceinline__ void stage_wh(
    uint32_t sb, int buf,
    const __nv_bfloat16* __restrict__ W1, const __nv_bfloat16* __restrict__ W2,
    int rb, int k0, int tid)
{
    uint32_t base = sb + buf * DSM_STRIDE;
    #pragma unroll
    for (int q = 0; q < 4; q++) {
        int idx = tid + q * 256;
        int r = idx >> 3, uu = idx & 7;
        uint32_t dst = SW128((uint32_t)(r * 128 + uu * 16));
        size_t so = (size_t)(rb + r) * 512 + k0 + uu * 8;
        cpasync16(base + DSM_W1 + dst, W1 + so);
        cpasync16(base + DSM_W2 + dst, W2 + so);
    }
    #pragma unroll
    for (int q = 0; q < 2; q++) {
        int idx = tid + q * 256;
        int b = idx >> 3, uu = idx & 7;
        uint32_t dst = SW128((uint32_t)(b * 128 + uu * 16));
        size_t so = (size_t)b * 512 + k0 + uu * 8;
        cpasync16(base + DSM_H1 + dst, g_hb[0] + so);
        cpasync16(base + DSM_H2 + dst, g_hb[1] + so);
    }
    asm volatile("cp.async.commit_group;" ::: "memory");
}

// ---- shared 3-pass HMMA mainloop over nc 64-k chunks ----
__device__ __forceinline__ void mma_mainloop(
    uint32_t sb, int tid, int wid, int lid,
    const __nv_bfloat16* W1, const __nv_bfloat16* W2,
    int rb, int kstart, int nc, float acc[8][4])
{
    const int sel = lid >> 3, row = lid & 7;
    const int aV  = 16 * wid + ((sel & 1) << 3) + row;
    const int aKo = (sel >> 1) << 3;
    const int bB  = ((sel >> 1) << 3) + row;
    const int bKo = (sel & 1) << 3;

    stage_wh(sb, 0, W1, W2, rb, kstart, tid);
    for (int c = 0; c < nc; c++) {
        if (c < nc - 1) {
            stage_wh(sb, (c + 1) & 1, W1, W2, rb, kstart + (c + 1) * 64, tid);
            asm volatile("cp.async.wait_group 1;" ::: "memory");
        } else {
            asm volatile("cp.async.wait_group 0;" ::: "memory");
        }
        __syncthreads();
        const uint32_t base = sb + (c & 1) * DSM_STRIDE;

        #pragma unroll
        for (int kk = 0; kk < 64; kk += 16) {
            uint32_t a1[4], a2[4];
            uint32_t aoff = SW128((uint32_t)(aV * 128 + (kk + aKo) * 2));
            ldsm4(a1, base + DSM_W1 + aoff);
            ldsm4(a2, base + DSM_W2 + aoff);
            #pragma unroll
            for (int jp = 0; jp < 4; jp++) {
                uint32_t b1[4], b2[4];
                uint32_t boff = SW128((uint32_t)((16 * jp + bB) * 128 + (kk + bKo) * 2));
                ldsm4(b1, base + DSM_H1 + boff);
                ldsm4(b2, base + DSM_H2 + boff);
                mma16816(acc[2 * jp],     a1, b1[0], b1[1]);
                mma16816(acc[2 * jp + 1], a1, b1[2], b1[3]);
                mma16816(acc[2 * jp],     a1, b2[0], b2[1]);
                mma16816(acc[2 * jp + 1], a1, b2[2], b2[3]);
                mma16816(acc[2 * jp],     a2, b1[0], b1[1]);
                mma16816(acc[2 * jp + 1], a2, b1[2], b1[3]);
            }
        }
        __syncthreads();
    }
}

// =========================================================
// k_prep: ih gate partials (needs argmax(t-1)). grid 32, 256 thr.
//  bid -> rblk = bid>>1 (128-row block), khalf = bid&1. Planes 0,1.
//  x = embed[tok] gathered + split to bf16 during staging.
// =========================================================
__global__ __launch_bounds__(256) void k_prep(
    int t, const void* __restrict__ captions, const float* __restrict__ embed)
{
    extern __shared__ char dsm[];
    __shared__ int stok[B_];
    const uint32_t sb = smem_u32(dsm);
    const int tid = threadIdx.x;
    const int bid = blockIdx.x;
    const int wid = tid >> 5, lid = tid & 31;
    const int rb    = (bid >> 1) * 128;
    const int kbase = (bid & 1) * 256;

    if (t == 0 && bid == 0 && tid < 128)
        g_amax[tid >> 6][tid & 63] = 0ull;

    if (tid < B_) {
        int tok;
        if (t == 0) {
            const int* ci = (const int*)captions;
            bool is64 = true;
            #pragma unroll
            for (int i = 1; i < 32; i += 2) if (ci[i]) is64 = false;
            tok = is64 ? (int)((const long long*)captions)[tid] : ci[tid];
        } else {
            ull pk = g_amax[(t + 1) & 1][tid];
            tok = (int)(0x7FFFFFFFu - (unsigned)(pk & 0xFFFFFFFFull));
        }
        stok[tid] = tok;
    }
    __syncthreads();

    auto stage = [&](int buf, int c) {
        const int k0 = kbase + c * 64;
        uint32_t base = sb + buf * DSM_STRIDE;
        #pragma unroll
        for (int q = 0; q < 4; q++) {
            int idx = tid + q * 256;
            int r = idx >> 3, uu = idx & 7;
            uint32_t dst = SW128((uint32_t)(r * 128 + uu * 16));
            size_t so = (size_t)(rb + r) * 512 + k0 + uu * 8;
            cpasync16(base + DSM_W1 + dst, g_Ib1 + so);
            cpasync16(base + DSM_W2 + dst, g_Ib2 + so);
        }
        asm volatile("cp.async.commit_group;" ::: "memory");
        // gather embed rows, split fp32 -> bf16 hi/lo, STS
        #pragma unroll
        for (int q = 0; q < 4; q++) {
            int idx = tid + q * 256;
            int b = idx >> 4, kk = (idx & 15) * 4;
            float4 x = *(const float4*)(embed + (size_t)stok[b] * E_ + k0 + kk);
            __nv_bfloat16 hx = __float2bfloat16(x.x), hy = __float2bfloat16(x.y);
            __nv_bfloat16 hz = __float2bfloat16(x.z), hw = __float2bfloat16(x.w);
            __nv_bfloat162 hi0; hi0.x = hx; hi0.y = hy;
            __nv_bfloat162 hi1; hi1.x = hz; hi1.y = hw;
            __nv_bfloat162 lo0, lo1;
            lo0.x = __float2bfloat16(x.x - __bfloat162float(hx));
            lo0.y = __float2bfloat16(x.y - __bfloat162float(hy));
            lo1.x = __float2bfloat16(x.z - __bfloat162float(hz));
            lo1.y = __float2bfloat16(x.w - __bfloat162float(hw));
            uint32_t dst = SW128((uint32_t)(b * 128 + kk * 2));
            ull hp, lp;
            memcpy(&hp, &hi0, 4); memcpy(((char*)&hp) + 4, &hi1, 4);
            memcpy(&lp, &lo0, 4); memcpy(((char*)&lp) + 4, &lo1, 4);
            *(ull*)(dsm + buf * DSM_STRIDE + DSM_H1 + dst) = hp;
            *(ull*)(dsm + buf * DSM_STRIDE + DSM_H2 + dst) = lp;
        }
    };

    const int sel = lid >> 3, row = lid & 7;
    const int aV  = 16 * wid + ((sel & 1) << 3) + row;
    const int aKo = (sel >> 1) << 3;
    const int bB  = ((sel >> 1) << 3) + row;
    const int bKo = (sel & 1) << 3;

    float acc[8][4] = {};
    stage(0, 0);
    for (int c = 0; c < 4; c++) {
        if (c < 3) {
            stage((c + 1) & 1, c + 1);
            asm volatile("cp.async.wait_group 1;" ::: "memory");
        } else {
            asm volatile("cp.async.wait_group 0;" ::: "memory");
        }
        __syncthreads();
        const uint32_t base = sb + (c & 1) * DSM_STRIDE;
        #pragma unroll
        for (int kk = 0; kk < 64; kk += 16) {
            uint32_t a1[4], a2[4];
            uint32_t aoff = SW128((uint32_t)(aV * 128 + (kk + aKo) * 2));
            ldsm4(a1, base + DSM_W1 + aoff);
            ldsm4(a2, base + DSM_W2 + aoff);
            #pragma unroll
            for (int jp = 0; jp < 4; jp++) {
                uint32_t b1[4], b2[4];
                uint32_t boff = SW128((uint32_t)((16 * jp + bB) * 128 + (kk + bKo) * 2));
                ldsm4(b1, base + DSM_H1 + boff);
                ldsm4(b2, base + DSM_H2 + boff);
                mma16816(acc[2 * jp],     a1, b1[0], b1[1]);
                mma16816(acc[2 * jp + 1], a1, b1[2], b1[3]);
                mma16816(acc[2 * jp],     a1, b2[0], b2[1]);
                mma16816(acc[2 * jp + 1], a1, b2[2], b2[3]);
                mma16816(acc[2 * jp],     a2, b1[0], b1[1]);
                mma16816(acc[2 * jp + 1], a2, b1[2], b1[3]);
            }
        }
        __syncthreads();
    }

    float* gp = g_gates[bid & 1];
    const int qrow = lid >> 2, qcol = lid & 3;
    const int r0 = rb + 16 * wid + qrow;
    const int r1 = r0 + 8;
    #pragma unroll
    for (int j = 0; j < 8; j++) {
        int blo = 8 * j + 2 * qcol, bhi = blo + 1;
        gp[(size_t)blo * G4 + r0] = acc[j][0];
        gp[(size_t)bhi * G4 + r0] = acc[j][1];
        gp[(size_t)blo * G4 + r1] = acc[j][2];
        gp[(size_t)bhi * G4 + r1] = acc[j][3];
    }
}

// =========================================================
// k_update: sum 4 planes + biases, LSTM nonlin, write h + bf16 splits.
// =========================================================
__global__ __launch_bounds__(256) void k_update(
    int t, const float* __restrict__ features,
    const float* __restrict__ b_ih, const float* __restrict__ b_hh)
{
    int idx = blockIdx.x * 256 + threadIdx.x;
    int b = idx >> 9, j = idx & 511;
    const int base = b * G4;

    float z[4];
    #pragma unroll
    for (int g = 0; g < 4; g++) {
        int o = base + j + g * 512;
        z[g] = b_ih[j + g * 512] + b_hh[j + g * 512]
             + g_gates[0][o] + g_gates[1][o] + g_gates[2][o] + g_gates[3][o];
    }
    float i_ = 1.0f / (1.0f + expf(-z[0]));
    float f_ = 1.0f / (1.0f + expf(-z[1]));
    float gg = tanhf(z[2]);
    float o_ = 1.0f / (1.0f + expf(-z[3]));

    float c_old = (t == 0) ? features[b * H_ + j] : g_c[b * H_ + j];
    float c_new = f_ * c_old + i_ * gg;
    float h_new = o_ * tanhf(c_new);

    g_c[b * H_ + j]        = c_new;
    g_h[t & 1][b * H_ + j] = h_new;

    __nv_bfloat16 h1 = __float2bfloat16(h_new);
    g_hb[0][b * 512 + j] = h1;
    g_hb[1][b * 512 + j] = __float2bfloat16(h_new - __bfloat162float(h1));
}

// =========================================================
// k_big: bids 0..249 = logits(t) (128v x 64b x 512k),
//        bids 250..281 = hh gate partials for t+1 (planes 2,3; skipped at t=T-1).
//        t<0: 32 gate-only blocks from features splits.
// =========================================================
__global__ __launch_bounds__(256) void k_big(
    int t, const float* __restrict__ lin_b, float* __restrict__ out)
{
    extern __shared__ char dsm[];
    __shared__ ull s_amax[64];
    const uint32_t sb = smem_u32(dsm);
    const int tid = threadIdx.x;
    const int bid = blockIdx.x;
    const int wid = tid >> 5, lid = tid & 31;
    const int qrow = lid >> 2, qcol = lid & 3;

    if (t < 0 || bid >= 250) {
        // ---- hh gates for next step ----
        if (t >= T_ - 1) return;
        const int gid = (t < 0) ? bid : bid - 250;
        const int rb    = (gid >> 1) * 128;
        const int kbase = (gid & 1) * 256;
        float acc[8][4] = {};
        mma_mainloop(sb, tid, wid, lid, g_Hb1, g_Hb2, rb, kbase, 4, acc);

        float* gp = g_gates[2 + (gid & 1)];
        const int r0 = rb + 16 * wid + qrow;
        const int r1 = r0 + 8;
        #pragma unroll
        for (int j = 0; j < 8; j++) {
            int blo = 8 * j + 2 * qcol, bhi = blo + 1;
            gp[(size_t)blo * G4 + r0] = acc[j][0];
            gp[(size_t)bhi * G4 + r0] = acc[j][1];
            gp[(size_t)blo * G4 + r1] = acc[j][2];
            gp[(size_t)bhi * G4 + r1] = acc[j][3];
        }
        return;
    }

    // ---- logits ----
    const int vb = bid * 128;
    if (tid < 64) s_amax[tid] = 0ull;
    if (bid == 0 && tid < 64) g_amax[(t + 1) & 1][tid] = 0ull;

    float acc[8][4] = {};
    mma_mainloop(sb, tid, wid, lid, g_Wb1, g_Wb2, vb, 0, 8, acc);

    const int v0 = vb + 16 * wid + qrow;
    const int v1 = v0 + 8;
    const float bi0 = lin_b[v0], bi1 = lin_b[v1];

    #pragma unroll
    for (int j = 0; j < 8; j++) {
        int blo = 8 * j + 2 * qcol, bhi = blo + 1;
        float c0 = acc[j][0] + bi0;
        float c1 = acc[j][1] + bi0;
        float c2 = acc[j][2] + bi1;
        float c3 = acc[j][3] + bi1;
        out[((size_t)blo * T_ + t) * V_ + v0] = c0;
        out[((size_t)bhi * T_ + t) * V_ + v0] = c1;
        out[((size_t)blo * T_ + t) * V_ + v1] = c2;
        out[((size_t)bhi * T_ + t) * V_ + v1] = c3;

        ull klo = ((ull)fkey(c0) << 32) | (ull)(0x7FFFFFFFu - (unsigned)v0);
        ull k2  = ((ull)fkey(c2) << 32) | (ull)(0x7FFFFFFFu - (unsigned)v1);
        if (k2 > klo) klo = k2;
        ull khi = ((ull)fkey(c1) << 32) | (ull)(0x7FFFFFFFu - (unsigned)v0);
        k2      = ((ull)fkey(c3) << 32) | (ull)(0x7FFFFFFFu - (unsigned)v1);
        if (k2 > khi) khi = k2;
        #pragma unroll
        for (int s = 4; s < 32; s <<= 1) {
            ull o1 = __shfl_xor_sync(0xFFFFFFFFu, klo, s); if (o1 > klo) klo = o1;
            ull o2 = __shfl_xor_sync(0xFFFFFFFFu, khi, s); if (o2 > khi) khi = o2;
        }
        if (lid < 4) {
            atomicMax(&s_amax[blo], klo);
            atomicMax(&s_amax[bhi], khi);
        }
    }
    __syncthreads();
    if (tid < 64) atomicMax(&g_amax[t & 1][tid], s_amax[tid]);
}

// =========================================================
extern "C" void kernel_launch(void* const* d_in, const int* in_sizes, int n_in,
                              void* d_out, int out_size)
{
    const float* features = (const float*)d_in[0];
    const void*  captions = d_in[1];
    int off = (in_sizes[2] == V_ * E_) ? 0 : 1;   // 'lengths' may be materialized
    const float* embed = (const float*)d_in[2 + off];
    const float* W_ih  = (const float*)d_in[3 + off];
    const float* W_hh  = (const float*)d_in[4 + off];
    const float* b_ih  = (const float*)d_in[5 + off];
    const float* b_hh  = (const float*)d_in[6 + off];
    const float* lin_W = (const float*)d_in[7 + off];
    const float* lin_b = (const float*)d_in[8 + off];
    float* out = (float*)d_out;
    (void)n_in; (void)out_size;

    cudaFuncSetAttribute(k_big,  cudaFuncAttributeMaxDynamicSharedMemorySize, DSM_TOT);
    cudaFuncSetAttribute(k_prep, cudaFuncAttributeMaxDynamicSharedMemorySize, DSM_TOT);

    // one-time prologue: all bf16 splits, then hh planes for t=0 (h(-1)=features)
    k_splitall<<<72320, 256>>>(lin_W, W_ih, W_hh, features);
    k_big<<<32, 256, DSM_TOT>>>(-1, lin_b, out);

    for (int t = 0; t < T_; t++) {
        k_prep<<<32, 256, DSM_TOT>>>(t, captions, embed);
        k_update<<<128, 256>>>(t, features, b_ih, b_hh);
        k_big<<<282, 256, DSM_TOT>>>(t, lin_b, out);
    }
}